// round 11
// baseline (speedup 1.0000x reference)
#include <cuda_runtime.h>
#include <cuda_fp16.h>

// Sinkhorn (B=8, 1024x1024, lambda=10, 100 iters, uniform marginals).
// Persistent kernel: 8 batches x 16 blocks, 1024 threads, 1 block/SM.
// K tile (64 rows x 1024 cols, fp16*32) resident in SMEM.
// Per iteration: phaseA tiled partial (8x8 per thread) -> SMEM tree-reduce ->
// fp16 partial to L2 -> ONE per-batch barrier -> every block reduces all 16
// partials -> v in SMEM -> phaseB u update (2 rows/warp).
// Final P = u * exp(-10*min(M,5)) (fp32) * v. Deterministic reduction order.

#define BB    8
#define NN    1024
#define NH    512          // half2 columns
#define GG    16
#define RPB   64
#define NT    1024
#define ITERS 100
#define RINV  (1.0f/1024.0f)
#define KSCALE 32.0f

// SMEM: Ks[64][512] half2 (131072) + red[8][512] float2 (32768)
//       + v_s[1024] float (4096) + u_s[64] float (256)
#define KS_BYTES   (RPB*NH*4)
#define RED_BYTES  (8*NH*8)
#define SMEM_BYTES (KS_BYTES + RED_BYTES + NN*4 + RPB*4)

__device__ __half2  g_wp[2][BB][GG][NH];   // double-buffered fp16 partials
__device__ unsigned g_bar[BB][32];         // one 128B line per batch

__global__ void zero_bar_kernel() {
    if (threadIdx.x < BB) g_bar[threadIdx.x][0] = 0u;
}

static __device__ __forceinline__ unsigned ld_acq(const unsigned* p) {
    unsigned v;
    asm volatile("ld.acquire.gpu.global.u32 %0, [%1];" : "=r"(v) : "l"(p) : "memory");
    return v;
}
static __device__ __forceinline__ void red_rel_add1(unsigned* p) {
    asm volatile("red.release.gpu.global.add.u32 [%0], 1;" :: "l"(p) : "memory");
}

__global__ void __launch_bounds__(NT, 1)
sinkhorn_persistent(const float* __restrict__ Min, float* __restrict__ out)
{
    extern __shared__ unsigned char smraw[];
    __half2* Ks   = reinterpret_cast<__half2*>(smraw);                    // [64][512]
    float2*  redb = reinterpret_cast<float2*>(smraw + KS_BYTES);          // [8][512]
    float*   v_s  = reinterpret_cast<float*>(smraw + KS_BYTES + RED_BYTES); // [1024]
    float*   u_s  = v_s + NN;                                             // [64]

    const int bid  = blockIdx.x;
    const int b    = bid >> 4;
    const int g    = bid & (GG - 1);
    const int t    = threadIdx.x;
    const int lane = t & 31;
    const int wrp  = t >> 5;
    const int rowgrp = t >> 7;     // 0..7  (phase A: rows [8*rowgrp, 8*rowgrp+8))
    const int cg     = t & 127;    // 0..127 (phase A: h2cols [4cg, 4cg+4))

    const size_t base = ((size_t)b * NN + (size_t)g * RPB) * NN;
    const float2* M2  = reinterpret_cast<const float2*>(Min + base);

    // ---- Prologue: build scaled fp16 K tile in SMEM ----
    for (int idx = t; idx < RPB * NH; idx += NT) {
        float2 m = M2[idx];
        float k0 = KSCALE * __expf(-10.0f * fminf(m.x, 5.0f));
        float k1 = KSCALE * __expf(-10.0f * fminf(m.y, 5.0f));
        Ks[idx] = __floats2half2_rn(k0, k1);
    }
    if (t < RPB) u_s[t] = RINV;
    __syncthreads();

    unsigned* ctr = &g_bar[b][0];

    for (int it = 0; it <= ITERS; ++it) {
        const int buf = it & 1;

        // ---- Phase A: 8-row x 4-half2 tile per thread, fp32 accumulation ----
        {
            const float4* u4 = reinterpret_cast<const float4*>(u_s);
            float4 ulo = u4[rowgrp * 2], uhi = u4[rowgrp * 2 + 1];
            float ua[8] = {ulo.x, ulo.y, ulo.z, ulo.w, uhi.x, uhi.y, uhi.z, uhi.w};
            float2 a0 = {0.f,0.f}, a1 = {0.f,0.f}, a2 = {0.f,0.f}, a3 = {0.f,0.f};
            #pragma unroll
            for (int r8 = 0; r8 < 8; ++r8) {
                const int r = rowgrp * 8 + r8;
                uint4 k4 = reinterpret_cast<const uint4*>(Ks + r * NH)[cg];
                float ur = ua[r8];
                float2 f;
                f = __half22float2(*reinterpret_cast<__half2*>(&k4.x));
                a0.x = fmaf(f.x, ur, a0.x); a0.y = fmaf(f.y, ur, a0.y);
                f = __half22float2(*reinterpret_cast<__half2*>(&k4.y));
                a1.x = fmaf(f.x, ur, a1.x); a1.y = fmaf(f.y, ur, a1.y);
                f = __half22float2(*reinterpret_cast<__half2*>(&k4.z));
                a2.x = fmaf(f.x, ur, a2.x); a2.y = fmaf(f.y, ur, a2.y);
                f = __half22float2(*reinterpret_cast<__half2*>(&k4.w));
                a3.x = fmaf(f.x, ur, a3.x); a3.y = fmaf(f.y, ur, a3.y);
            }
            float4* rr = reinterpret_cast<float4*>(redb + rowgrp * NH + 4 * cg);
            rr[0] = make_float4(a0.x, a0.y, a1.x, a1.y);
            rr[1] = make_float4(a2.x, a2.y, a3.x, a3.y);
        }
        __syncthreads();

        // ---- Within-block tree over 8 row-groups -> fp16 partial to L2 ----
        if (t < NH) {
            float2 w = {0.f, 0.f};
            #pragma unroll
            for (int g8 = 0; g8 < 8; ++g8) {
                float2 p = redb[g8 * NH + t];
                w.x += p.x; w.y += p.y;
            }
            __stcg(&g_wp[buf][b][g][t], __floats2half2_rn(w.x, w.y));
        }

        // ---- Single per-batch barrier ----
        __syncthreads();
        if (t == 0) {
            red_rel_add1(ctr);
            const unsigned target = (unsigned)(it + 1) * GG;
            while (ld_acq(ctr) < target) { }
        }
        __syncthreads();

        // ---- Cross-block reduce: all 16 partials for my 2 columns -> v ----
        if (t < NH) {
            float w0 = 0.f, w1 = 0.f;
            #pragma unroll
            for (int p = 0; p < GG; ++p) {
                float2 f = __half22float2(__ldcg(&g_wp[buf][b][p][t]));
                w0 += f.x; w1 += f.y;
            }
            float2 vv;
            vv.x = __fdividef(RINV, w0);   // = v_true / KSCALE
            vv.y = __fdividef(RINV, w1);
            reinterpret_cast<float2*>(v_s)[t] = vv;
        }
        __syncthreads();

        if (it < ITERS) {
            // ---- Phase B: warp wrp handles rows {2*wrp, 2*wrp+1} ----
            const float4* v4p = reinterpret_cast<const float4*>(v_s);
            float4 vA[4], vB[4];
            #pragma unroll
            for (int q = 0; q < 4; ++q) {
                vA[q] = v4p[2 * (lane + 32 * q)];
                vB[q] = v4p[2 * (lane + 32 * q) + 1];
            }
            #pragma unroll
            for (int k = 0; k < 2; ++k) {
                const int r = wrp * 2 + k;
                const uint4* row = reinterpret_cast<const uint4*>(Ks + r * NH);
                float s0 = 0.f, s1 = 0.f, s2 = 0.f, s3 = 0.f;
                #pragma unroll
                for (int q = 0; q < 4; ++q) {
                    uint4 k4 = row[lane + 32 * q];
                    float2 f;
                    f = __half22float2(*reinterpret_cast<__half2*>(&k4.x));
                    s0 = fmaf(f.x, vA[q].x, s0); s0 = fmaf(f.y, vA[q].y, s0);
                    f = __half22float2(*reinterpret_cast<__half2*>(&k4.y));
                    s1 = fmaf(f.x, vA[q].z, s1); s1 = fmaf(f.y, vA[q].w, s1);
                    f = __half22float2(*reinterpret_cast<__half2*>(&k4.z));
                    s2 = fmaf(f.x, vB[q].x, s2); s2 = fmaf(f.y, vB[q].y, s2);
                    f = __half22float2(*reinterpret_cast<__half2*>(&k4.w));
                    s3 = fmaf(f.x, vB[q].z, s3); s3 = fmaf(f.y, vB[q].w, s3);
                }
                float s = (s0 + s1) + (s2 + s3);
                #pragma unroll
                for (int off = 16; off; off >>= 1)
                    s += __shfl_xor_sync(0xffffffffu, s, off);
                if (lane == 0) u_s[r] = __fdividef(RINV, s);
            }
            __syncthreads();
        }
    }

    // ---- Epilogue: P = u * exp(-10*min(M,5)) * (KSCALE * v), fp32 K ----
    {
        float2* out2 = reinterpret_cast<float2*>(out + base);
        const float2* v2p = reinterpret_cast<const float2*>(v_s);
        for (int idx = t; idx < RPB * NH; idx += NT) {
            const int r = idx >> 9;
            const int c = idx & (NH - 1);
            float ur = u_s[r];
            float2 vv = v2p[c];
            float2 m = M2[idx];
            float2 o;
            o.x = ur * __expf(-10.0f * fminf(m.x, 5.0f)) * (KSCALE * vv.x);
            o.y = ur * __expf(-10.0f * fminf(m.y, 5.0f)) * (KSCALE * vv.y);
            out2[idx] = o;
        }
    }
}

extern "C" void kernel_launch(void* const* d_in, const int* in_sizes, int n_in,
                              void* d_out, int out_size) {
    (void)in_sizes; (void)n_in; (void)out_size;
    const float* M = (const float*)d_in[0];
    float* out = (float*)d_out;

    cudaFuncSetAttribute(sinkhorn_persistent,
                         cudaFuncAttributeMaxDynamicSharedMemorySize, SMEM_BYTES);

    zero_bar_kernel<<<1, 32>>>();
    sinkhorn_persistent<<<BB * GG, NT, SMEM_BYTES>>>(M, out);
}

// round 14
// speedup vs baseline: 1.2555x; 1.2555x over previous
#include <cuda_runtime.h>
#include <cuda_fp16.h>

// Sinkhorn (B=8, 1024x1024, lambda=10, 100 iters, uniform marginals).
// Persistent kernel: 8 batches x 16 blocks, 512 threads, 1 block/SM,
// K tile (64x1024, fp16*32) resident in SMEM. R10 skeleton (one per-batch
// barrier/iter, fp16 partials in L2, all-blocks-reduce-all) with packed
// HFMA2 math + short-chain fp32 promotion in both sweeps.
// Epilogue P = u * exp(-10*min(M,5)) (fp32) * v stays full fp32.

#define BB    8
#define NN    1024
#define NH    512          // half2 columns
#define GG    16
#define RPB   64
#define NT    512
#define ITERS 100
#define RINV  (1.0f/1024.0f)
#define KSCALE 32.0f

// SMEM layout (bytes): Ks | v_h | v_s | u_s | u_hp
#define KS_BYTES  (RPB*NH*4)                 // 131072
#define VH_OFF    (KS_BYTES)                 // half2[512]  (2048 B)
#define VS_OFF    (VH_OFF + NH*4)            // float[1024] (4096 B)
#define US_OFF    (VS_OFF + NN*4)            // float[64]   (256 B)
#define UHP_OFF   (US_OFF + 256)             // half2[64]   (256 B)
#define SMEM_BYTES (UHP_OFF + 256)           // 137728

__device__ __half2  g_wp[2][BB][GG][NH];   // double-buffered fp16 partials
__device__ unsigned g_bar[BB][32];         // one 128B line per batch

__global__ void zero_bar_kernel() {
    if (threadIdx.x < BB) g_bar[threadIdx.x][0] = 0u;
}

static __device__ __forceinline__ unsigned ld_acq(const unsigned* p) {
    unsigned v;
    asm volatile("ld.acquire.gpu.global.u32 %0, [%1];" : "=r"(v) : "l"(p) : "memory");
    return v;
}
static __device__ __forceinline__ void red_rel_add1(unsigned* p) {
    asm volatile("red.release.gpu.global.add.u32 [%0], 1;" :: "l"(p) : "memory");
}
static __device__ __forceinline__ __half2 u2h2(unsigned x) {
    return *reinterpret_cast<__half2*>(&x);
}

__global__ void __launch_bounds__(NT, 1)
sinkhorn_persistent(const float* __restrict__ Min, float* __restrict__ out)
{
    extern __shared__ unsigned char smraw[];
    __half2* Ks   = reinterpret_cast<__half2*>(smraw);            // [64][512]
    __half2* v_h  = reinterpret_cast<__half2*>(smraw + VH_OFF);   // [512]
    float*   v_s  = reinterpret_cast<float*>(smraw + VS_OFF);     // [1024]
    float*   u_s  = reinterpret_cast<float*>(smraw + US_OFF);     // [64]
    __half2* u_hp = reinterpret_cast<__half2*>(smraw + UHP_OFF);  // [64] (u,u) pairs

    const int bid  = blockIdx.x;
    const int b    = bid >> 4;
    const int g    = bid & (GG - 1);
    const int t    = threadIdx.x;
    const int lane = t & 31;
    const int wrp  = t >> 5;

    const size_t base = ((size_t)b * NN + (size_t)g * RPB) * NN;
    const float2* M2  = reinterpret_cast<const float2*>(Min + base);

    // ---- Prologue: build scaled fp16 K tile in SMEM ----
    for (int idx = t; idx < RPB * NH; idx += NT) {
        float2 m = M2[idx];
        float k0 = KSCALE * __expf(-10.0f * fminf(m.x, 5.0f));
        float k1 = KSCALE * __expf(-10.0f * fminf(m.y, 5.0f));
        Ks[idx] = __floats2half2_rn(k0, k1);
    }
    if (t < RPB) {
        u_s[t]  = RINV;
        u_hp[t] = __floats2half2_rn(RINV, RINV);
    }
    __syncthreads();

    unsigned* ctr = &g_bar[b][0];

    for (int it = 0; it <= ITERS; ++it) {
        const int buf = it & 1;

        // ---- Phase A: thread t owns cols {2t,2t+1}; HFMA2 over 64 rows,
        //      two interleaved fp16 chains, promote to fp32 every 16 rows ----
        {
            const uint4* uq = reinterpret_cast<const uint4*>(u_hp); // 16 x (4 u-pairs)
            float2 accf = {0.f, 0.f};
            #pragma unroll
            for (int c16 = 0; c16 < 4; ++c16) {
                __half2 h0 = __float2half2_rn(0.f);
                __half2 h1 = __float2half2_rn(0.f);
                #pragma unroll
                for (int r4 = 0; r4 < 4; ++r4) {
                    uint4 up = uq[c16 * 4 + r4];           // broadcast LDS.128
                    const int rb = (c16 * 4 + r4) * 4;
                    h0 = __hfma2(Ks[(rb + 0) * NH + t], u2h2(up.x), h0);
                    h1 = __hfma2(Ks[(rb + 1) * NH + t], u2h2(up.y), h1);
                    h0 = __hfma2(Ks[(rb + 2) * NH + t], u2h2(up.z), h0);
                    h1 = __hfma2(Ks[(rb + 3) * NH + t], u2h2(up.w), h1);
                }
                float2 f0 = __half22float2(h0);
                float2 f1 = __half22float2(h1);
                accf.x += f0.x + f1.x;
                accf.y += f0.y + f1.y;
            }
            __stcg(&g_wp[buf][b][g][t], __floats2half2_rn(accf.x, accf.y));
        }

        // ---- Single per-batch barrier ----
        __syncthreads();
        if (t == 0) {
            red_rel_add1(ctr);
            const unsigned target = (unsigned)(it + 1) * GG;
            while (ld_acq(ctr) < target) { }
        }
        __syncthreads();

        // ---- Cross-block reduce: 16 partials for my 2 cols -> v (f32 + h2) ----
        {
            float w0 = 0.f, w1 = 0.f;
            #pragma unroll
            for (int p = 0; p < GG; ++p) {
                float2 f = __half22float2(__ldcg(&g_wp[buf][b][p][t]));
                w0 += f.x; w1 += f.y;
            }
            float2 vv;
            vv.x = __fdividef(RINV, w0);   // = v_true / KSCALE
            vv.y = __fdividef(RINV, w1);
            reinterpret_cast<float2*>(v_s)[t] = vv;
            v_h[t] = __floats2half2_rn(vv.x, vv.y);
        }
        __syncthreads();

        if (it < ITERS) {
            // ---- Phase B: warp wrp handles rows [4*wrp, 4*wrp+4);
            //      fp16 dot in 8-term chains, promote per uint4 chunk ----
            const uint4* vh4 = reinterpret_cast<const uint4*>(v_h); // 128 uint4
            uint4 vh[4];
            #pragma unroll
            for (int q = 0; q < 4; ++q) vh[q] = vh4[lane + 32 * q];

            #pragma unroll
            for (int k = 0; k < 4; ++k) {
                const int r = wrp * 4 + k;
                const uint4* row = reinterpret_cast<const uint4*>(Ks + r * NH);
                float2 s2 = {0.f, 0.f};
                #pragma unroll
                for (int q = 0; q < 4; ++q) {
                    uint4 k4 = row[lane + 32 * q];
                    __half2 a = __hmul2(u2h2(k4.x), u2h2(vh[q].x));
                    a = __hfma2(u2h2(k4.y), u2h2(vh[q].y), a);
                    a = __hfma2(u2h2(k4.z), u2h2(vh[q].z), a);
                    a = __hfma2(u2h2(k4.w), u2h2(vh[q].w), a);
                    float2 f = __half22float2(a);
                    s2.x += f.x; s2.y += f.y;
                }
                float s = s2.x + s2.y;
                #pragma unroll
                for (int off = 16; off; off >>= 1)
                    s += __shfl_xor_sync(0xffffffffu, s, off);
                if (lane == 0) {
                    float uf = __fdividef(RINV, s);
                    u_s[r]  = uf;
                    u_hp[r] = __floats2half2_rn(uf, uf);
                }
            }
            __syncthreads();
        }
    }

    // ---- Epilogue: P = u * exp(-10*min(M,5)) * (KSCALE * v), all fp32 ----
    {
        float2* out2 = reinterpret_cast<float2*>(out + base);
        const float2* v2p = reinterpret_cast<const float2*>(v_s);
        for (int idx = t; idx < RPB * NH; idx += NT) {
            const int r = idx >> 9;
            const int c = idx & (NH - 1);
            float ur = u_s[r];
            float2 vv = v2p[c];
            float2 m = M2[idx];
            float2 o;
            o.x = ur * __expf(-10.0f * fminf(m.x, 5.0f)) * (KSCALE * vv.x);
            o.y = ur * __expf(-10.0f * fminf(m.y, 5.0f)) * (KSCALE * vv.y);
            out2[idx] = o;
        }
    }
}

extern "C" void kernel_launch(void* const* d_in, const int* in_sizes, int n_in,
                              void* d_out, int out_size) {
    (void)in_sizes; (void)n_in; (void)out_size;
    const float* M = (const float*)d_in[0];
    float* out = (float*)d_out;

    cudaFuncSetAttribute(sinkhorn_persistent,
                         cudaFuncAttributeMaxDynamicSharedMemorySize, SMEM_BYTES);

    zero_bar_kernel<<<1, 32>>>();
    sinkhorn_persistent<<<BB * GG, NT, SMEM_BYTES>>>(M, out);
}

// round 16
// speedup vs baseline: 1.3738x; 1.0942x over previous
#include <cuda_runtime.h>
#include <cuda_fp16.h>

// Sinkhorn (B=8, 1024x1024, lambda=10, 100 iters, uniform marginals).
// Persistent kernel: 8 batches x 16 blocks, 512 threads, 1 block/SM.
// K tile (64x1024, fp16*KSCALE) resident in SMEM.
// FUSED sweep: per warp-row, dot(K[r,:],v) -> u_r -> immediately accumulate
// u_r*K[r,:] (row still in registers) into fp16 w chains. One Ks pass/iter.
// Warp partials -> SMEM tree -> fp16 partial to L2 -> ONE per-batch barrier
// -> every block reduces all 16 partials -> v. Deterministic everywhere.
// Epilogue P = u * exp(-10*min(M,5)) (fp32) * v.

#define BB    8
#define NN    1024
#define NH    512          // half2 columns
#define GG    16
#define RPB   64
#define NT    512
#define NWARP 16
#define ITERS 100
#define RINV  (1.0f/1024.0f)
#define KSCALE 32.0f

// SMEM: Ks[64][512]h2 | redb[16][512]h2 | v_h[512]h2 | v_s f32[1024] | u_s f32[64]
#define KS_BYTES   (RPB*NH*4)                  // 131072
#define REDB_OFF   (KS_BYTES)                  // 32768
#define VH_OFF     (REDB_OFF + NWARP*NH*4)     // 2048
#define VS_OFF     (VH_OFF + NH*4)             // 4096
#define US_OFF     (VS_OFF + NN*4)             // 256
#define SMEM_BYTES (US_OFF + 256)              // 170240

__device__ __half2  g_wp[2][BB][GG][NH];   // double-buffered fp16 partials
__device__ unsigned g_bar[BB][32];         // one 128B line per batch

__global__ void zero_bar_kernel() {
    if (threadIdx.x < BB) g_bar[threadIdx.x][0] = 0u;
}

static __device__ __forceinline__ unsigned ld_acq(const unsigned* p) {
    unsigned v;
    asm volatile("ld.acquire.gpu.global.u32 %0, [%1];" : "=r"(v) : "l"(p) : "memory");
    return v;
}
static __device__ __forceinline__ void red_rel_add1(unsigned* p) {
    asm volatile("red.release.gpu.global.add.u32 [%0], 1;" :: "l"(p) : "memory");
}
static __device__ __forceinline__ __half2 u2h2(unsigned x) {
    return *reinterpret_cast<__half2*>(&x);
}
static __device__ __forceinline__ unsigned h2u(__half2 h) {
    return *reinterpret_cast<unsigned*>(&h);
}

__global__ void __launch_bounds__(NT, 1)
sinkhorn_persistent(const float* __restrict__ Min, float* __restrict__ out)
{
    extern __shared__ unsigned char smraw[];
    __half2* Ks   = reinterpret_cast<__half2*>(smraw);             // [64][512]
    __half2* redb = reinterpret_cast<__half2*>(smraw + REDB_OFF);  // [16][512]
    __half2* v_h  = reinterpret_cast<__half2*>(smraw + VH_OFF);    // [512]
    float*   v_s  = reinterpret_cast<float*>(smraw + VS_OFF);      // [1024]
    float*   u_s  = reinterpret_cast<float*>(smraw + US_OFF);      // [64]

    const int bid  = blockIdx.x;
    const int b    = bid >> 4;
    const int g    = bid & (GG - 1);
    const int t    = threadIdx.x;
    const int lane = t & 31;
    const int wrp  = t >> 5;

    const size_t base = ((size_t)b * NN + (size_t)g * RPB) * NN;
    const float2* M2  = reinterpret_cast<const float2*>(Min + base);

    // ---- Prologue: build scaled fp16 K tile in SMEM ----
    for (int idx = t; idx < RPB * NH; idx += NT) {
        float2 m = M2[idx];
        float k0 = KSCALE * __expf(-10.0f * fminf(m.x, 5.0f));
        float k1 = KSCALE * __expf(-10.0f * fminf(m.y, 5.0f));
        Ks[idx] = __floats2half2_rn(k0, k1);
    }
    if (t < RPB) u_s[t] = RINV;
    __syncthreads();

    // ---- Initial partial^0 from uniform u0 = RINV (warp's 4 rows) ----
    {
        const __half2 uh = __floats2half2_rn(RINV, RINV);
        __half2 wh[16];
        #pragma unroll
        for (int j = 0; j < 16; ++j) wh[j] = __floats2half2_rn(0.f, 0.f);
        #pragma unroll
        for (int k = 0; k < 4; ++k) {
            const uint4* row = reinterpret_cast<const uint4*>(Ks + (wrp * 4 + k) * NH);
            #pragma unroll
            for (int q = 0; q < 4; ++q) {
                uint4 k4 = row[lane + 32 * q];
                wh[4*q+0] = __hfma2(u2h2(k4.x), uh, wh[4*q+0]);
                wh[4*q+1] = __hfma2(u2h2(k4.y), uh, wh[4*q+1]);
                wh[4*q+2] = __hfma2(u2h2(k4.z), uh, wh[4*q+2]);
                wh[4*q+3] = __hfma2(u2h2(k4.w), uh, wh[4*q+3]);
            }
        }
        uint4* rb = reinterpret_cast<uint4*>(redb + wrp * NH);
        #pragma unroll
        for (int q = 0; q < 4; ++q)
            rb[lane + 32*q] = make_uint4(h2u(wh[4*q]), h2u(wh[4*q+1]),
                                         h2u(wh[4*q+2]), h2u(wh[4*q+3]));
    }
    __syncthreads();
    {   // tree reduce -> partial^0 to L2 (buf 0)
        float w0 = 0.f, w1 = 0.f;
        #pragma unroll
        for (int w = 0; w < NWARP; ++w) {
            float2 f = __half22float2(redb[w * NH + t]);
            w0 += f.x; w1 += f.y;
        }
        __stcg(&g_wp[0][b][g][t], __floats2half2_rn(w0, w1));
    }

    unsigned* ctr = &g_bar[b][0];

    for (int it = 0; it <= ITERS; ++it) {
        const int buf = it & 1;

        // ---- Single per-batch barrier ----
        __syncthreads();
        if (t == 0) {
            red_rel_add1(ctr);
            const unsigned target = (unsigned)(it + 1) * GG;
            while (ld_acq(ctr) < target) { }
        }
        __syncthreads();

        // ---- Cross-block reduce: 16 partials for my 2 cols -> v ----
        {
            float w0 = 0.f, w1 = 0.f;
            #pragma unroll
            for (int p = 0; p < GG; ++p) {
                float2 f = __half22float2(__ldcg(&g_wp[buf][b][p][t]));
                w0 += f.x; w1 += f.y;
            }
            float2 vv;
            vv.x = __fdividef(RINV, w0);   // = v_true / KSCALE
            vv.y = __fdividef(RINV, w1);
            reinterpret_cast<float2*>(v_s)[t] = vv;
            v_h[t] = __floats2half2_rn(vv.x, vv.y);
        }
        if (it == ITERS) break;
        __syncthreads();

        // ---- FUSED pass: warp wrp rows [4w,4w+4): dot -> u_r -> w accum ----
        {
            const uint4* vh4 = reinterpret_cast<const uint4*>(v_h);
            uint4 vh[4];
            #pragma unroll
            for (int q = 0; q < 4; ++q) vh[q] = vh4[lane + 32 * q];

            __half2 wh[16];
            #pragma unroll
            for (int j = 0; j < 16; ++j) wh[j] = __floats2half2_rn(0.f, 0.f);

            #pragma unroll
            for (int k = 0; k < 4; ++k) {
                const int r = wrp * 4 + k;
                const uint4* row = reinterpret_cast<const uint4*>(Ks + r * NH);
                uint4 k4[4];
                #pragma unroll
                for (int q = 0; q < 4; ++q) k4[q] = row[lane + 32 * q];

                // dot: fp16 4-chains, promote per chunk (as R14 phase B)
                float s = 0.f;
                #pragma unroll
                for (int q = 0; q < 4; ++q) {
                    __half2 a = __hmul2(u2h2(k4[q].x), u2h2(vh[q].x));
                    a = __hfma2(u2h2(k4[q].y), u2h2(vh[q].y), a);
                    a = __hfma2(u2h2(k4[q].z), u2h2(vh[q].z), a);
                    a = __hfma2(u2h2(k4[q].w), u2h2(vh[q].w), a);
                    float2 f = __half22float2(a);
                    s += f.x + f.y;
                }
                #pragma unroll
                for (int off = 16; off; off >>= 1)
                    s += __shfl_xor_sync(0xffffffffu, s, off);

                const float uf = __fdividef(RINV, s);
                if (lane == 0) u_s[r] = uf;
                const __half2 uh2v = __float2half2_rn(uf);

                // reuse row registers: accumulate u_r * K[r,:] into w chains
                #pragma unroll
                for (int q = 0; q < 4; ++q) {
                    wh[4*q+0] = __hfma2(u2h2(k4[q].x), uh2v, wh[4*q+0]);
                    wh[4*q+1] = __hfma2(u2h2(k4[q].y), uh2v, wh[4*q+1]);
                    wh[4*q+2] = __hfma2(u2h2(k4[q].z), uh2v, wh[4*q+2]);
                    wh[4*q+3] = __hfma2(u2h2(k4[q].w), uh2v, wh[4*q+3]);
                }
            }
            uint4* rb = reinterpret_cast<uint4*>(redb + wrp * NH);
            #pragma unroll
            for (int q = 0; q < 4; ++q)
                rb[lane + 32*q] = make_uint4(h2u(wh[4*q]), h2u(wh[4*q+1]),
                                             h2u(wh[4*q+2]), h2u(wh[4*q+3]));
        }
        __syncthreads();

        // ---- Tree reduce over 16 warp partials -> partial^{it+1} to L2 ----
        {
            float w0 = 0.f, w1 = 0.f;
            #pragma unroll
            for (int w = 0; w < NWARP; ++w) {
                float2 f = __half22float2(redb[w * NH + t]);
                w0 += f.x; w1 += f.y;
            }
            __stcg(&g_wp[buf ^ 1][b][g][t], __floats2half2_rn(w0, w1));
        }
    }
    __syncthreads();

    // ---- Epilogue: P = u * exp(-10*min(M,5)) * (KSCALE * v), all fp32 ----
    {
        float2* out2 = reinterpret_cast<float2*>(out + base);
        const float2* v2p = reinterpret_cast<const float2*>(v_s);
        for (int idx = t; idx < RPB * NH; idx += NT) {
            const int r = idx >> 9;
            const int c = idx & (NH - 1);
            float ur = u_s[r];
            float2 vv = v2p[c];
            float2 m = M2[idx];
            float2 o;
            o.x = ur * __expf(-10.0f * fminf(m.x, 5.0f)) * (KSCALE * vv.x);
            o.y = ur * __expf(-10.0f * fminf(m.y, 5.0f)) * (KSCALE * vv.y);
            out2[idx] = o;
        }
    }
}

extern "C" void kernel_launch(void* const* d_in, const int* in_sizes, int n_in,
                              void* d_out, int out_size) {
    (void)in_sizes; (void)n_in; (void)out_size;
    const float* M = (const float*)d_in[0];
    float* out = (float*)d_out;

    cudaFuncSetAttribute(sinkhorn_persistent,
                         cudaFuncAttributeMaxDynamicSharedMemorySize, SMEM_BYTES);

    zero_bar_kernel<<<1, 32>>>();
    sinkhorn_persistent<<<BB * GG, NT, SMEM_BYTES>>>(M, out);
}